// round 1
// baseline (speedup 1.0000x reference)
#include <cuda_runtime.h>

#define NN 100000
#define NE 1600000
#define D1 128
#define H4 4

// ---------------- scratch (device globals; no runtime allocation) -------------
__device__ float g_t[NN * D1];      // transformed features for current layer
__device__ float g_prev[NN * D1];   // layer input / residual carrier
__device__ float g_acc[NN * D1];    // scatter accumulator
__device__ float g_asrc[NN * H4];
__device__ float g_adst[NN * H4];
__device__ float g_m[NN * H4];      // segment max
__device__ float g_s[NN * H4];      // segment sum (edges only; self-loop added in finish)

__device__ __forceinline__ float lrelu(float x) { return x > 0.f ? x : 0.2f * x; }

// float atomic max via signed/unsigned int ordering trick
__device__ __forceinline__ void atomicMaxF(float* a, float v) {
    if (v >= 0.f) atomicMax((int*)a, __float_as_int(v));
    else          atomicMin((unsigned int*)a, (unsigned int)__float_as_int(v));
}

// vectorized global reduction (sm_90+): 16B per op instead of 4 scalar atomics
__device__ __forceinline__ void red4(float* p, float a, float b, float c, float d) {
    asm volatile("red.global.add.v4.f32 [%0], {%1,%2,%3,%4};"
                 :: "l"(p), "f"(a), "f"(b), "f"(c), "f"(d) : "memory");
}

// ---------------- layer 1 GEMM: x[N,16] @ W1[16,128] + logits + init ----------
__global__ void k_gemm1(const float* __restrict__ x, const float* __restrict__ W,
                        const float* __restrict__ aS, const float* __restrict__ aD) {
    int t = threadIdx.x;
    int nb = blockIdx.x * 8;
    __shared__ float xs[8][16];
    { int j = t >> 4, k = t & 15; xs[j][k] = x[(nb + j) * 16 + k]; }
    __syncthreads();

    float acc[8];
#pragma unroll
    for (int j = 0; j < 8; j++) acc[j] = 0.f;
#pragma unroll
    for (int k = 0; k < 16; k++) {
        float wv = W[k * 128 + t];
#pragma unroll
        for (int j = 0; j < 8; j++) acc[j] = fmaf(xs[j][k], wv, acc[j]);
    }

    float as_ = aS[t], ad_ = aD[t];
#pragma unroll
    for (int j = 0; j < 8; j++) {
        int n = nb + j;
        g_t[n * 128 + t] = acc[j];
        g_acc[n * 128 + t] = 0.f;
        float ps = acc[j] * as_, pd = acc[j] * ad_;
#pragma unroll
        for (int o = 16; o; o >>= 1) {
            ps += __shfl_xor_sync(0xffffffffu, ps, o);
            pd += __shfl_xor_sync(0xffffffffu, pd, o);
        }
        if ((t & 31) == 0) {
            int hd = t >> 5;
            g_asrc[n * 4 + hd] = ps;
            g_adst[n * 4 + hd] = pd;
            g_m[n * 4 + hd] = lrelu(ps + pd);   // self-loop logit seeds the max
            g_s[n * 4 + hd] = 0.f;
        }
    }
}

// ---------------- layer 2 GEMM: g_prev[N,128] @ W2[128,128] -------------------
__global__ void k_gemm2(const float* __restrict__ W,
                        const float* __restrict__ aS, const float* __restrict__ aD) {
    int t = threadIdx.x;
    int nb = blockIdx.x * 8;
    __shared__ float xs[8][128];
    for (int i = t; i < 1024; i += 128) xs[i >> 7][i & 127] = g_prev[nb * 128 + i];
    __syncthreads();

    float acc[8];
#pragma unroll
    for (int j = 0; j < 8; j++) acc[j] = 0.f;
#pragma unroll 4
    for (int k = 0; k < 128; k++) {
        float wv = W[k * 128 + t];
#pragma unroll
        for (int j = 0; j < 8; j++) acc[j] = fmaf(xs[j][k], wv, acc[j]);
    }

    float as_ = aS[t], ad_ = aD[t];
#pragma unroll
    for (int j = 0; j < 8; j++) {
        int n = nb + j;
        g_t[n * 128 + t] = acc[j];
        g_acc[n * 128 + t] = 0.f;
        float ps = acc[j] * as_, pd = acc[j] * ad_;
#pragma unroll
        for (int o = 16; o; o >>= 1) {
            ps += __shfl_xor_sync(0xffffffffu, ps, o);
            pd += __shfl_xor_sync(0xffffffffu, pd, o);
        }
        if ((t & 31) == 0) {
            int hd = t >> 5;
            g_asrc[n * 4 + hd] = ps;
            g_adst[n * 4 + hd] = pd;
            g_m[n * 4 + hd] = lrelu(ps + pd);
            g_s[n * 4 + hd] = 0.f;
        }
    }
}

// ---------------- layer 3 GEMM: g_prev[N,128] @ W3[128,32], 1 head ------------
__global__ void k_gemm3(const float* __restrict__ W,
                        const float* __restrict__ aS, const float* __restrict__ aD) {
    int t = threadIdx.x;
    int sub = t >> 5, c = t & 31;
    int nb = blockIdx.x * 4;
    int n = nb + sub;
    __shared__ float xs[4][128];
    for (int i = t; i < 512; i += 128) xs[i >> 7][i & 127] = g_prev[nb * 128 + i];
    __syncthreads();

    float acc = 0.f;
#pragma unroll 8
    for (int k = 0; k < 128; k++) acc = fmaf(xs[sub][k], W[k * 32 + c], acc);

    g_t[n * 32 + c] = acc;
    g_acc[n * 32 + c] = 0.f;
    float ps = acc * aS[c], pd = acc * aD[c];
#pragma unroll
    for (int o = 16; o; o >>= 1) {
        ps += __shfl_xor_sync(0xffffffffu, ps, o);
        pd += __shfl_xor_sync(0xffffffffu, pd, o);
    }
    if (c == 0) {
        g_asrc[n] = ps;
        g_adst[n] = pd;
        g_m[n] = lrelu(ps + pd);
        g_s[n] = 0.f;
    }
}

// ---------------- segment max over edges (4 heads / 1 head) -------------------
__global__ void k_max4(const int* __restrict__ src, const int* __restrict__ dst, int E) {
    int i = blockIdx.x * blockDim.x + threadIdx.x;
    if (i >= E) return;
    int sv = src[i], dv = dst[i];
    float4 as = *(const float4*)&g_asrc[sv * 4];
    float4 ad = *(const float4*)&g_adst[dv * 4];
    atomicMaxF(&g_m[dv * 4 + 0], lrelu(as.x + ad.x));
    atomicMaxF(&g_m[dv * 4 + 1], lrelu(as.y + ad.y));
    atomicMaxF(&g_m[dv * 4 + 2], lrelu(as.z + ad.z));
    atomicMaxF(&g_m[dv * 4 + 3], lrelu(as.w + ad.w));
}

__global__ void k_max1(const int* __restrict__ src, const int* __restrict__ dst, int E) {
    int i = blockIdx.x * blockDim.x + threadIdx.x;
    if (i >= E) return;
    int sv = src[i], dv = dst[i];
    atomicMaxF(&g_m[dv], lrelu(g_asrc[sv] + g_adst[dv]));
}

// ---------------- scatter: p = exp(e-m); s += p; acc[dst] += p*h[src] ---------
// warp per edge, 4 heads x 32 ch = 128 floats, each lane handles a float4
__global__ void k_scatter4(const int* __restrict__ src, const int* __restrict__ dst, int E) {
    int w = (blockIdx.x * blockDim.x + threadIdx.x) >> 5;
    int lane = threadIdx.x & 31;
    if (w >= E) return;
    int sv = 0, dv = 0;
    if (lane == 0) { sv = src[w]; dv = dst[w]; }
    sv = __shfl_sync(0xffffffffu, sv, 0);
    dv = __shfl_sync(0xffffffffu, dv, 0);
    float p = 0.f;
    if (lane < 4) {
        float e = lrelu(g_asrc[sv * 4 + lane] + g_adst[dv * 4 + lane]);
        p = __expf(e - g_m[dv * 4 + lane]);
        atomicAdd(&g_s[dv * 4 + lane], p);
    }
    float ph = __shfl_sync(0xffffffffu, p, lane >> 3);   // head = (lane*4)/32
    const float4 hv = *(const float4*)&g_t[sv * 128 + lane * 4];
    red4(&g_acc[dv * 128 + lane * 4], ph * hv.x, ph * hv.y, ph * hv.z, ph * hv.w);
}

// quarter-warp (8 lanes) per edge for layer 3 (1 head, 32 ch)
__global__ void k_scatter1(const int* __restrict__ src, const int* __restrict__ dst, int E) {
    int tid = blockIdx.x * blockDim.x + threadIdx.x;
    int e = tid >> 3;
    int j = tid & 7;
    if (e >= E) return;
    int sv = src[e], dv = dst[e];
    float p = __expf(lrelu(g_asrc[sv] + g_adst[dv]) - g_m[dv]);
    if (j == 0) atomicAdd(&g_s[dv], p);
    const float4 hv = *(const float4*)&g_t[sv * 32 + j * 4];
    red4(&g_acc[dv * 32 + j * 4], p * hv.x, p * hv.y, p * hv.z, p * hv.w);
}

// ---------------- finish: add self-loop, normalize, bias, ELU (+residual) -----
template <bool RES>
__global__ void k_finish(const float* __restrict__ b) {
    int n = blockIdx.x;
    int t = threadIdx.x;
    int hd = t >> 5;
    float e = lrelu(g_asrc[n * 4 + hd] + g_adst[n * 4 + hd]);
    float ps = __expf(e - g_m[n * 4 + hd]);
    float s = g_s[n * 4 + hd] + ps;
    float val = (g_acc[n * 128 + t] + ps * g_t[n * 128 + t]) / s + b[t];
    val = val > 0.f ? val : expm1f(val);
    if (RES) val += g_prev[n * 128 + t];
    g_prev[n * 128 + t] = val;
}

__global__ void k_finish3(const float* __restrict__ b3,
                          const float* __restrict__ rw, const float* __restrict__ rb,
                          const float* __restrict__ cw, const float* __restrict__ cb,
                          float* __restrict__ out) {
    int t = threadIdx.x;
    int sub = t >> 5, c = t & 31;
    int n = blockIdx.x * 4 + sub;
    float e = lrelu(g_asrc[n] + g_adst[n]);
    float ps = __expf(e - g_m[n]);
    float s = g_s[n] + ps;
    float val = (g_acc[n * 32 + c] + ps * g_t[n * 32 + c]) / s + b3[c];
    val = val > 0.f ? val : expm1f(val);
    float r = val * rw[c], cl = val * cw[c];
#pragma unroll
    for (int o = 16; o; o >>= 1) {
        r += __shfl_xor_sync(0xffffffffu, r, o);
        cl += __shfl_xor_sync(0xffffffffu, cl, o);
    }
    if (c == 0) {
        out[n] = r + rb[0];
        out[NN + n] = cl + cb[0];
    }
}

// ---------------- launch ------------------------------------------------------
extern "C" void kernel_launch(void* const* d_in, const int* in_sizes, int n_in,
                              void* d_out, int out_size) {
    const float* x    = (const float*)d_in[0];
    const int*   ei   = (const int*)d_in[1];
    const float* W1   = (const float*)d_in[2];
    const float* aS1  = (const float*)d_in[3];
    const float* aD1  = (const float*)d_in[4];
    const float* b1   = (const float*)d_in[5];
    const float* W2   = (const float*)d_in[6];
    const float* aS2  = (const float*)d_in[7];
    const float* aD2  = (const float*)d_in[8];
    const float* b2   = (const float*)d_in[9];
    const float* W3   = (const float*)d_in[10];
    const float* aS3  = (const float*)d_in[11];
    const float* aD3  = (const float*)d_in[12];
    const float* b3   = (const float*)d_in[13];
    const float* regw = (const float*)d_in[14];
    const float* regb = (const float*)d_in[15];
    const float* clsw = (const float*)d_in[16];
    const float* clsb = (const float*)d_in[17];
    float* out = (float*)d_out;

    const int* src = ei;
    const int* dst = ei + NE;

    // layer 1
    k_gemm1<<<NN / 8, 128>>>(x, W1, aS1, aD1);
    k_max4<<<(NE + 255) / 256, 256>>>(src, dst, NE);
    k_scatter4<<<(NE * 32 + 255) / 256, 256>>>(src, dst, NE);
    k_finish<false><<<NN, 128>>>(b1);

    // layer 2 (+ residual)
    k_gemm2<<<NN / 8, 128>>>(W2, aS2, aD2);
    k_max4<<<(NE + 255) / 256, 256>>>(src, dst, NE);
    k_scatter4<<<(NE * 32 + 255) / 256, 256>>>(src, dst, NE);
    k_finish<true><<<NN, 128>>>(b2);

    // layer 3 (1 head, 32 ch) + output heads
    k_gemm3<<<NN / 4, 128>>>(W3, aS3, aD3);
    k_max1<<<(NE + 255) / 256, 256>>>(src, dst, NE);
    k_scatter1<<<(NE * 8 + 255) / 256, 256>>>(src, dst, NE);
    k_finish3<<<NN / 4, 128>>>(b3, regw, regb, clsw, clsb, out);
}

// round 2
// speedup vs baseline: 1.4302x; 1.4302x over previous
#include <cuda_runtime.h>

#define NN 100000
#define NE 1600000
#define D1 128

// ---------------- scratch (device globals) ------------------------------------
__device__ float g_t[NN * D1];      // transformed features for current layer
__device__ float g_prev[NN * D1];   // layer input / residual carrier
__device__ float g_asrc[NN * 4];
__device__ float g_adst[NN * 4];
__device__ int   g_off[NN + 1];     // CSR offsets by dst
__device__ int   g_cur[NN];         // degree -> cursor
__device__ int   g_csrc[NE];        // src node per CSR slot

__device__ __forceinline__ float lrelu(float x) { return x > 0.f ? x : 0.2f * x; }

// ---------------- CSR build ----------------------------------------------------
__global__ void k_zero() {
    int i = blockIdx.x * blockDim.x + threadIdx.x;
    if (i < NN) g_cur[i] = 0;
}

__global__ void k_hist(const int* __restrict__ dst) {
    int i = blockIdx.x * blockDim.x + threadIdx.x;
    if (i < NE) atomicAdd(&g_cur[dst[i]], 1);
}

__global__ void k_scan() {   // single block, 1024 threads, ~98 elems each
    __shared__ int sm[1024];
    const int CH = (NN + 1023) / 1024;
    int t = threadIdx.x;
    int lo = t * CH, hi = min(lo + CH, NN);
    int sum = 0;
    for (int i = lo; i < hi; i++) sum += g_cur[i];
    sm[t] = sum;
    __syncthreads();
    for (int o = 1; o < 1024; o <<= 1) {
        int v = 0;
        if (t >= o) v = sm[t - o];
        __syncthreads();
        if (t >= o) sm[t] += v;
        __syncthreads();
    }
    int run = (t == 0) ? 0 : sm[t - 1];
    for (int i = lo; i < hi; i++) {
        int d = g_cur[i];
        g_off[i] = run;
        g_cur[i] = run;
        run += d;
    }
    if (t == 1023) g_off[NN] = run;
}

__global__ void k_reorder(const int* __restrict__ src, const int* __restrict__ dst) {
    int i = blockIdx.x * blockDim.x + threadIdx.x;
    if (i >= NE) return;
    int pos = atomicAdd(&g_cur[dst[i]], 1);
    g_csrc[pos] = src[i];
}

// ---------------- layer 1 GEMM: x[N,16] @ W1[16,128] + logits ------------------
__global__ void k_gemm1(const float* __restrict__ x, const float* __restrict__ W,
                        const float* __restrict__ aS, const float* __restrict__ aD) {
    int t = threadIdx.x;
    int nb = blockIdx.x * 8;
    __shared__ float xs[8][16];
    { int j = t >> 4, k = t & 15; xs[j][k] = x[(nb + j) * 16 + k]; }
    __syncthreads();

    float acc[8];
#pragma unroll
    for (int j = 0; j < 8; j++) acc[j] = 0.f;
#pragma unroll
    for (int k = 0; k < 16; k++) {
        float wv = W[k * 128 + t];
#pragma unroll
        for (int j = 0; j < 8; j++) acc[j] = fmaf(xs[j][k], wv, acc[j]);
    }

    float as_ = aS[t], ad_ = aD[t];
#pragma unroll
    for (int j = 0; j < 8; j++) {
        int n = nb + j;
        g_t[n * 128 + t] = acc[j];
        float ps = acc[j] * as_, pd = acc[j] * ad_;
#pragma unroll
        for (int o = 16; o; o >>= 1) {
            ps += __shfl_xor_sync(0xffffffffu, ps, o);
            pd += __shfl_xor_sync(0xffffffffu, pd, o);
        }
        if ((t & 31) == 0) {
            int hd = t >> 5;
            g_asrc[n * 4 + hd] = ps;
            g_adst[n * 4 + hd] = pd;
        }
    }
}

// ---------------- layer 2 GEMM: g_prev[N,128] @ W2[128,128], 16 rows/block -----
__global__ void k_gemm2(const float* __restrict__ W,
                        const float* __restrict__ aS, const float* __restrict__ aD) {
    int t = threadIdx.x;
    int nb = blockIdx.x * 16;
    __shared__ float xs[16][128];
    for (int i = t; i < 2048; i += 128) xs[i >> 7][i & 127] = g_prev[nb * 128 + i];
    __syncthreads();

    float acc[16];
#pragma unroll
    for (int j = 0; j < 16; j++) acc[j] = 0.f;
#pragma unroll 4
    for (int k = 0; k < 128; k++) {
        float wv = W[k * 128 + t];
#pragma unroll
        for (int j = 0; j < 16; j++) acc[j] = fmaf(xs[j][k], wv, acc[j]);
    }

    float as_ = aS[t], ad_ = aD[t];
#pragma unroll
    for (int j = 0; j < 16; j++) {
        int n = nb + j;
        g_t[n * 128 + t] = acc[j];
        float ps = acc[j] * as_, pd = acc[j] * ad_;
#pragma unroll
        for (int o = 16; o; o >>= 1) {
            ps += __shfl_xor_sync(0xffffffffu, ps, o);
            pd += __shfl_xor_sync(0xffffffffu, pd, o);
        }
        if ((t & 31) == 0) {
            int hd = t >> 5;
            g_asrc[n * 4 + hd] = ps;
            g_adst[n * 4 + hd] = pd;
        }
    }
}

// ---------------- layer 3 GEMM: g_prev[N,128] @ W3[128,32], 1 head -------------
__global__ void k_gemm3(const float* __restrict__ W,
                        const float* __restrict__ aS, const float* __restrict__ aD) {
    int t = threadIdx.x;
    int sub = t >> 5, c = t & 31;
    int nb = blockIdx.x * 4;
    int n = nb + sub;
    __shared__ float xs[4][128];
    for (int i = t; i < 512; i += 128) xs[i >> 7][i & 127] = g_prev[nb * 128 + i];
    __syncthreads();

    float acc = 0.f;
#pragma unroll 8
    for (int k = 0; k < 128; k++) acc = fmaf(xs[sub][k], W[k * 32 + c], acc);

    g_t[n * 32 + c] = acc;
    float ps = acc * aS[c], pd = acc * aD[c];
#pragma unroll
    for (int o = 16; o; o >>= 1) {
        ps += __shfl_xor_sync(0xffffffffu, ps, o);
        pd += __shfl_xor_sync(0xffffffffu, pd, o);
    }
    if (c == 0) {
        g_asrc[n] = ps;
        g_adst[n] = pd;
    }
}

// ---------------- fused gather: softmax + aggregate + finish (4 heads) ---------
// warp per dst node; no atomics.
template <bool RES>
__global__ void k_gather4(const float* __restrict__ b) {
    int n = (blockIdx.x * blockDim.x + threadIdx.x) >> 5;
    if (n >= NN) return;
    int lane = threadIdx.x & 31;
    int beg = g_off[n], end = g_off[n + 1];

    float4 ad = *(const float4*)&g_adst[n * 4];
    float4 asf = *(const float4*)&g_asrc[n * 4];

    // pass 1: segment max per head, seeded by self-loop
    float m0 = lrelu(asf.x + ad.x), m1 = lrelu(asf.y + ad.y);
    float m2 = lrelu(asf.z + ad.z), m3 = lrelu(asf.w + ad.w);
    for (int i = beg + lane; i < end; i += 32) {
        int sv = g_csrc[i];
        float4 as = *(const float4*)&g_asrc[sv * 4];
        m0 = fmaxf(m0, lrelu(as.x + ad.x));
        m1 = fmaxf(m1, lrelu(as.y + ad.y));
        m2 = fmaxf(m2, lrelu(as.z + ad.z));
        m3 = fmaxf(m3, lrelu(as.w + ad.w));
    }
#pragma unroll
    for (int o = 16; o; o >>= 1) {
        m0 = fmaxf(m0, __shfl_xor_sync(0xffffffffu, m0, o));
        m1 = fmaxf(m1, __shfl_xor_sync(0xffffffffu, m1, o));
        m2 = fmaxf(m2, __shfl_xor_sync(0xffffffffu, m2, o));
        m3 = fmaxf(m3, __shfl_xor_sync(0xffffffffu, m3, o));
    }

    // per-lane head constants (lanes 0..3 compute p for head==lane)
    int hl = lane & 3;
    float ml  = (hl == 0) ? m0 : (hl == 1) ? m1 : (hl == 2) ? m2 : m3;
    float adl = (hl == 0) ? ad.x : (hl == 1) ? ad.y : (hl == 2) ? ad.z : ad.w;

    // pass 2: sequential edges, gather h[src] rows, accumulate in registers
    float4 acc = make_float4(0.f, 0.f, 0.f, 0.f);
    float s = 0.f;
    int hsrc = lane >> 3;   // which lane's p this lane consumes
    int i = beg;
    for (; i + 1 < end; i += 2) {
        int sv0 = g_csrc[i], sv1 = g_csrc[i + 1];
        float a0 = g_asrc[sv0 * 4 + hl];
        float a1 = g_asrc[sv1 * 4 + hl];
        const float4 h0 = *(const float4*)&g_t[sv0 * 128 + lane * 4];
        const float4 h1 = *(const float4*)&g_t[sv1 * 128 + lane * 4];
        float p0 = __expf(lrelu(a0 + adl) - ml);
        float p1 = __expf(lrelu(a1 + adl) - ml);
        if (lane < 4) s += p0 + p1;
        float ph0 = __shfl_sync(0xffffffffu, p0, hsrc);
        float ph1 = __shfl_sync(0xffffffffu, p1, hsrc);
        acc.x = fmaf(ph0, h0.x, acc.x); acc.y = fmaf(ph0, h0.y, acc.y);
        acc.z = fmaf(ph0, h0.z, acc.z); acc.w = fmaf(ph0, h0.w, acc.w);
        acc.x = fmaf(ph1, h1.x, acc.x); acc.y = fmaf(ph1, h1.y, acc.y);
        acc.z = fmaf(ph1, h1.z, acc.z); acc.w = fmaf(ph1, h1.w, acc.w);
    }
    if (i < end) {
        int sv = g_csrc[i];
        float a0 = g_asrc[sv * 4 + hl];
        const float4 h0 = *(const float4*)&g_t[sv * 128 + lane * 4];
        float p0 = __expf(lrelu(a0 + adl) - ml);
        if (lane < 4) s += p0;
        float ph0 = __shfl_sync(0xffffffffu, p0, hsrc);
        acc.x = fmaf(ph0, h0.x, acc.x); acc.y = fmaf(ph0, h0.y, acc.y);
        acc.z = fmaf(ph0, h0.z, acc.z); acc.w = fmaf(ph0, h0.w, acc.w);
    }

    // self-loop term
    float asl = (hl == 0) ? asf.x : (hl == 1) ? asf.y : (hl == 2) ? asf.z : asf.w;
    float pself = __expf(lrelu(asl + adl) - ml);
    if (lane < 4) s += pself;
    float sh  = __shfl_sync(0xffffffffu, s, hsrc);
    float psh = __shfl_sync(0xffffffffu, pself, hsrc);

    const float4 ts = *(const float4*)&g_t[n * 128 + lane * 4];
    const float4 bv = *(const float4*)&b[lane * 4];
    float inv = 1.f / sh;
    float4 v;
    v.x = fmaf(psh, ts.x, acc.x) * inv + bv.x;
    v.y = fmaf(psh, ts.y, acc.y) * inv + bv.y;
    v.z = fmaf(psh, ts.z, acc.z) * inv + bv.z;
    v.w = fmaf(psh, ts.w, acc.w) * inv + bv.w;
    v.x = v.x > 0.f ? v.x : expm1f(v.x);
    v.y = v.y > 0.f ? v.y : expm1f(v.y);
    v.z = v.z > 0.f ? v.z : expm1f(v.z);
    v.w = v.w > 0.f ? v.w : expm1f(v.w);
    float4* po = (float4*)&g_prev[n * 128 + lane * 4];
    if (RES) {
        float4 pr = *po;
        v.x += pr.x; v.y += pr.y; v.z += pr.z; v.w += pr.w;
    }
    *po = v;
}

// ---------------- fused gather layer 3 (1 head, 32 ch) + output heads ----------
__global__ void k_gather1(const float* __restrict__ b3,
                          const float* __restrict__ rw, const float* __restrict__ rb,
                          const float* __restrict__ cw, const float* __restrict__ cb,
                          float* __restrict__ out) {
    int n = (blockIdx.x * blockDim.x + threadIdx.x) >> 5;
    if (n >= NN) return;
    int lane = threadIdx.x & 31;
    int beg = g_off[n], end = g_off[n + 1];

    float adn = g_adst[n];
    float asn = g_asrc[n];
    float m = lrelu(asn + adn);
    for (int i = beg + lane; i < end; i += 32)
        m = fmaxf(m, lrelu(g_asrc[g_csrc[i]] + adn));
#pragma unroll
    for (int o = 16; o; o >>= 1)
        m = fmaxf(m, __shfl_xor_sync(0xffffffffu, m, o));

    float acc = 0.f, s = 0.f;
    int i = beg;
    for (; i + 1 < end; i += 2) {
        int sv0 = g_csrc[i], sv1 = g_csrc[i + 1];
        float a0 = g_asrc[sv0], a1 = g_asrc[sv1];
        float h0 = g_t[sv0 * 32 + lane], h1 = g_t[sv1 * 32 + lane];
        float p0 = __expf(lrelu(a0 + adn) - m);
        float p1 = __expf(lrelu(a1 + adn) - m);
        s += p0 + p1;
        acc = fmaf(p0, h0, acc);
        acc = fmaf(p1, h1, acc);
    }
    if (i < end) {
        int sv = g_csrc[i];
        float p = __expf(lrelu(g_asrc[sv] + adn) - m);
        s += p;
        acc = fmaf(p, g_t[sv * 32 + lane], acc);
    }

    float ps = __expf(lrelu(asn + adn) - m);
    s += ps;
    float val = fmaf(ps, g_t[n * 32 + lane], acc) / s + b3[lane];
    val = val > 0.f ? val : expm1f(val);

    float r = val * rw[lane], cl = val * cw[lane];
#pragma unroll
    for (int o = 16; o; o >>= 1) {
        r += __shfl_xor_sync(0xffffffffu, r, o);
        cl += __shfl_xor_sync(0xffffffffu, cl, o);
    }
    if (lane == 0) {
        out[n] = r + rb[0];
        out[NN + n] = cl + cb[0];
    }
}

// ---------------- launch ------------------------------------------------------
extern "C" void kernel_launch(void* const* d_in, const int* in_sizes, int n_in,
                              void* d_out, int out_size) {
    const float* x    = (const float*)d_in[0];
    const int*   ei   = (const int*)d_in[1];
    const float* W1   = (const float*)d_in[2];
    const float* aS1  = (const float*)d_in[3];
    const float* aD1  = (const float*)d_in[4];
    const float* b1   = (const float*)d_in[5];
    const float* W2   = (const float*)d_in[6];
    const float* aS2  = (const float*)d_in[7];
    const float* aD2  = (const float*)d_in[8];
    const float* b2   = (const float*)d_in[9];
    const float* W3   = (const float*)d_in[10];
    const float* aS3  = (const float*)d_in[11];
    const float* aD3  = (const float*)d_in[12];
    const float* b3   = (const float*)d_in[13];
    const float* regw = (const float*)d_in[14];
    const float* regb = (const float*)d_in[15];
    const float* clsw = (const float*)d_in[16];
    const float* clsb = (const float*)d_in[17];
    float* out = (float*)d_out;

    const int* src = ei;
    const int* dst = ei + NE;

    // CSR by dst (rebuilt every call; graph-capturable, no allocation)
    k_zero<<<(NN + 255) / 256, 256>>>();
    k_hist<<<(NE + 255) / 256, 256>>>(dst);
    k_scan<<<1, 1024>>>();
    k_reorder<<<(NE + 255) / 256, 256>>>(src, dst);

    // layer 1
    k_gemm1<<<NN / 8, 128>>>(x, W1, aS1, aD1);
    k_gather4<false><<<(NN * 32 + 255) / 256, 256>>>(b1);

    // layer 2 (+ residual)
    k_gemm2<<<NN / 16, 128>>>(W2, aS2, aD2);
    k_gather4<true><<<(NN * 32 + 255) / 256, 256>>>(b2);

    // layer 3 + output heads
    k_gemm3<<<NN / 4, 128>>>(W3, aS3, aD3);
    k_gather1<<<(NN * 32 + 255) / 256, 256>>>(b3, regw, regb, clsw, clsb, out);
}

// round 3
// speedup vs baseline: 2.4807x; 1.7344x over previous
#include <cuda_runtime.h>

#define NN 100000
#define NE 1600000
#define D1 128

// ---------------- scratch (device globals) ------------------------------------
__device__ float g_t[NN * D1];      // transformed features (layer 2: 128, layer 3: 32)
__device__ float g_prev[NN * D1];   // layer output / residual carrier
__device__ float g_asrc[NN * 4];
__device__ float g_adst[NN * 4];
__device__ int   g_off[NN + 1];     // CSR offsets by dst
__device__ int   g_cur[NN];         // degree -> cursor
__device__ int   g_csrc[NE];        // src node per CSR slot
__device__ int   g_bsum[512];
__device__ int   g_boff[512];
__device__ float g_vs[64];          // W1 @ attS per head  [h][k]
__device__ float g_vd[64];          // W1 @ attD per head

__device__ __forceinline__ float lrelu(float x) { return x > 0.f ? x : 0.2f * x; }
__device__ __forceinline__ float pexp(float x) { return __expf(fminf(x, 80.f)); }
__device__ __forceinline__ float elu(float x) { return x > 0.f ? x : expm1f(x); }

// ================= CSR build ====================================================
__global__ void k_zero() {
    int i = blockIdx.x * blockDim.x + threadIdx.x;
    if (i < NN) g_cur[i] = 0;
}

__global__ void k_hist(const int* __restrict__ dst) {
    int i = blockIdx.x * blockDim.x + threadIdx.x;
    if (i < NE) atomicAdd(&g_cur[dst[i]], 1);
}

__global__ void k_bsum() {
    __shared__ int sm[256];
    int b = blockIdx.x, t = threadIdx.x;
    int i = b * 256 + t;
    sm[t] = (i < NN) ? g_cur[i] : 0;
    __syncthreads();
    for (int o = 128; o; o >>= 1) {
        if (t < o) sm[t] += sm[t + o];
        __syncthreads();
    }
    if (t == 0) g_bsum[b] = sm[0];
}

__global__ void k_bscan() {   // 1 block, 512 threads: exclusive scan of 391 sums
    __shared__ int sm[512];
    int t = threadIdx.x;
    int v = (t < 391) ? g_bsum[t] : 0;
    sm[t] = v;
    __syncthreads();
    for (int o = 1; o < 512; o <<= 1) {
        int u = (t >= o) ? sm[t - o] : 0;
        __syncthreads();
        sm[t] += u;
        __syncthreads();
    }
    if (t < 391) g_boff[t] = sm[t] - v;
    if (t == 0) g_off[NN] = NE;
}

__global__ void k_local() {
    __shared__ int sm[256];
    int b = blockIdx.x, t = threadIdx.x;
    int i = b * 256 + t;
    int v = (i < NN) ? g_cur[i] : 0;
    sm[t] = v;
    __syncthreads();
    for (int o = 1; o < 256; o <<= 1) {
        int u = (t >= o) ? sm[t - o] : 0;
        __syncthreads();
        sm[t] += u;
        __syncthreads();
    }
    if (i < NN) {
        int off = g_boff[b] + sm[t] - v;
        g_off[i] = off;
        g_cur[i] = off;
    }
}

__global__ void k_reorder(const int* __restrict__ src, const int* __restrict__ dst) {
    int i = blockIdx.x * blockDim.x + threadIdx.x;
    if (i >= NE) return;
    int pos = atomicAdd(&g_cur[dst[i]], 1);
    g_csrc[pos] = src[i];
}

// ================= layer 1: logits directly from x ==============================
// v_s[h][k] = sum_c W1[k, h*32+c] * aS[h][c]  (a_src = x . v_s)
__global__ void k_prep1(const float* __restrict__ W, const float* __restrict__ aS,
                        const float* __restrict__ aD) {
    int t = threadIdx.x;       // 64 threads: t = h*16 + k
    int h = t >> 4, k = t & 15;
    float vs = 0.f, vd = 0.f;
#pragma unroll
    for (int c = 0; c < 32; c++) {
        float wv = W[k * 128 + h * 32 + c];
        vs = fmaf(wv, aS[h * 32 + c], vs);
        vd = fmaf(wv, aD[h * 32 + c], vd);
    }
    g_vs[t] = vs;
    g_vd[t] = vd;
}

__global__ void k_logits1(const float* __restrict__ x) {
    int t = blockIdx.x * blockDim.x + threadIdx.x;  // t = n*4 + h
    if (t >= NN * 4) return;
    int n = t >> 2, h = t & 3;
    const float* xr = &x[n * 16];
    float as = 0.f, ad = 0.f;
#pragma unroll
    for (int k = 0; k < 16; k++) {
        float xv = xr[k];
        as = fmaf(xv, g_vs[h * 16 + k], as);
        ad = fmaf(xv, g_vd[h * 16 + k], ad);
    }
    g_asrc[t] = as;
    g_adst[t] = ad;
}

// ---- layer-1 gather in x-space: agg[h][k] = sum p_h * x[src][k]; out = agg@W1 --
__global__ void k_gx(const float* __restrict__ x, const float* __restrict__ W,
                     const float* __restrict__ b) {
    __shared__ float Ws[16 * 128];
    __shared__ float agg[8][64];
    int t = threadIdx.x;
    {   // stage W1 (8KB) once per block
        float4* wd = (float4*)Ws;
        const float4* wsrc = (const float4*)W;
        wd[t] = wsrc[t];
        wd[t + 256] = wsrc[t + 256];
    }
    __syncthreads();

    int n = (blockIdx.x * blockDim.x + t) >> 5;
    if (n >= NN) return;
    int lane = t & 31;
    int w = t >> 5;
    int k = lane & 15;
    int half = lane >> 4;
    int beg = g_off[n], end = g_off[n + 1];

    float4 ad = *(const float4*)&g_adst[n * 4];
    float4 acc = make_float4(0.f, 0.f, 0.f, 0.f);
    float4 s4 = make_float4(0.f, 0.f, 0.f, 0.f);

    for (int i = beg + half; i < end; i += 2) {
        int sv = g_csrc[i];
        float xv = __ldg(&x[sv * 16 + k]);
        float4 a = *(const float4*)&g_asrc[sv * 4];
        float4 p;
        p.x = pexp(lrelu(a.x + ad.x));
        p.y = pexp(lrelu(a.y + ad.y));
        p.z = pexp(lrelu(a.z + ad.z));
        p.w = pexp(lrelu(a.w + ad.w));
        s4.x += p.x; s4.y += p.y; s4.z += p.z; s4.w += p.w;
        acc.x = fmaf(p.x, xv, acc.x);
        acc.y = fmaf(p.y, xv, acc.y);
        acc.z = fmaf(p.z, xv, acc.z);
        acc.w = fmaf(p.w, xv, acc.w);
    }
    // combine even/odd halves
    acc.x += __shfl_xor_sync(0xffffffffu, acc.x, 16);
    acc.y += __shfl_xor_sync(0xffffffffu, acc.y, 16);
    acc.z += __shfl_xor_sync(0xffffffffu, acc.z, 16);
    acc.w += __shfl_xor_sync(0xffffffffu, acc.w, 16);
    s4.x += __shfl_xor_sync(0xffffffffu, s4.x, 16);
    s4.y += __shfl_xor_sync(0xffffffffu, s4.y, 16);
    s4.z += __shfl_xor_sync(0xffffffffu, s4.z, 16);
    s4.w += __shfl_xor_sync(0xffffffffu, s4.w, 16);

    // self loop
    {
        float4 a = *(const float4*)&g_asrc[n * 4];
        float4 p;
        p.x = pexp(lrelu(a.x + ad.x));
        p.y = pexp(lrelu(a.y + ad.y));
        p.z = pexp(lrelu(a.z + ad.z));
        p.w = pexp(lrelu(a.w + ad.w));
        s4.x += p.x; s4.y += p.y; s4.z += p.z; s4.w += p.w;
        float xv = x[n * 16 + k];
        acc.x = fmaf(p.x, xv, acc.x);
        acc.y = fmaf(p.y, xv, acc.y);
        acc.z = fmaf(p.z, xv, acc.z);
        acc.w = fmaf(p.w, xv, acc.w);
    }

    if (half == 0) {
        agg[w][k]      = acc.x;
        agg[w][16 + k] = acc.y;
        agg[w][32 + k] = acc.z;
        agg[w][48 + k] = acc.w;
    }
    __syncwarp();

    int hd = lane >> 3;
    float sh = (hd == 0) ? s4.x : (hd == 1) ? s4.y : (hd == 2) ? s4.z : s4.w;
    float inv = 1.f / sh;
    float4 o = make_float4(0.f, 0.f, 0.f, 0.f);
#pragma unroll
    for (int kk = 0; kk < 16; kk++) {
        float av = agg[w][hd * 16 + kk];
        float4 wv = *(const float4*)&Ws[kk * 128 + lane * 4];
        o.x = fmaf(av, wv.x, o.x);
        o.y = fmaf(av, wv.y, o.y);
        o.z = fmaf(av, wv.z, o.z);
        o.w = fmaf(av, wv.w, o.w);
    }
    float4 bv = *(const float4*)&b[lane * 4];
    o.x = elu(o.x * inv + bv.x);
    o.y = elu(o.y * inv + bv.y);
    o.z = elu(o.z * inv + bv.z);
    o.w = elu(o.w * inv + bv.w);
    *(float4*)&g_prev[n * 128 + lane * 4] = o;
}

// ================= layer 2 GEMM: g_prev[N,128] @ W2[128,128] ====================
// block 256 = 8 warps; warp handles 4 nodes x 128 cols; thread: 4 nodes x 4 cols
__global__ void k_gemm2(const float* __restrict__ W,
                        const float* __restrict__ aS, const float* __restrict__ aD) {
    __shared__ float xs[32][128];
    int t = threadIdx.x;
    int nb = blockIdx.x * 32;
    {
        const float4* srcp = (const float4*)&g_prev[nb * 128];
        float4* d = (float4*)xs;
#pragma unroll
        for (int r = 0; r < 4; r++) d[t + 256 * r] = srcp[t + 256 * r];
    }
    __syncthreads();

    int cg = t & 31;      // col group (also lane)
    int ng = t >> 5;      // warp -> nodes ng*4 .. +3
    float4 acc0 = make_float4(0,0,0,0), acc1 = acc0, acc2 = acc0, acc3 = acc0;
#pragma unroll 4
    for (int k = 0; k < 128; k++) {
        float4 wv = *(const float4*)&W[k * 128 + cg * 4];
        float x0 = xs[ng * 4 + 0][k];
        float x1 = xs[ng * 4 + 1][k];
        float x2 = xs[ng * 4 + 2][k];
        float x3 = xs[ng * 4 + 3][k];
        acc0.x = fmaf(x0, wv.x, acc0.x); acc0.y = fmaf(x0, wv.y, acc0.y);
        acc0.z = fmaf(x0, wv.z, acc0.z); acc0.w = fmaf(x0, wv.w, acc0.w);
        acc1.x = fmaf(x1, wv.x, acc1.x); acc1.y = fmaf(x1, wv.y, acc1.y);
        acc1.z = fmaf(x1, wv.z, acc1.z); acc1.w = fmaf(x1, wv.w, acc1.w);
        acc2.x = fmaf(x2, wv.x, acc2.x); acc2.y = fmaf(x2, wv.y, acc2.y);
        acc2.z = fmaf(x2, wv.z, acc2.z); acc2.w = fmaf(x2, wv.w, acc2.w);
        acc3.x = fmaf(x3, wv.x, acc3.x); acc3.y = fmaf(x3, wv.y, acc3.y);
        acc3.z = fmaf(x3, wv.z, acc3.z); acc3.w = fmaf(x3, wv.w, acc3.w);
    }

    float4 aSv = *(const float4*)&aS[cg * 4];
    float4 aDv = *(const float4*)&aD[cg * 4];
    float4 accs[4] = {acc0, acc1, acc2, acc3};
#pragma unroll
    for (int j = 0; j < 4; j++) {
        int node = nb + ng * 4 + j;
        *(float4*)&g_t[node * 128 + cg * 4] = accs[j];
        float ps = accs[j].x * aSv.x + accs[j].y * aSv.y + accs[j].z * aSv.z + accs[j].w * aSv.w;
        float pd = accs[j].x * aDv.x + accs[j].y * aDv.y + accs[j].z * aDv.z + accs[j].w * aDv.w;
#pragma unroll
        for (int o = 4; o; o >>= 1) {   // reduce within 8-lane (per-head) group
            ps += __shfl_xor_sync(0xffffffffu, ps, o);
            pd += __shfl_xor_sync(0xffffffffu, pd, o);
        }
        if ((cg & 7) == 0) {
            g_asrc[node * 4 + (cg >> 3)] = ps;
            g_adst[node * 4 + (cg >> 3)] = pd;
        }
    }
}

// ================= layer 2 gather (single pass, no max, unroll 4) ===============
__global__ void k_gather4(const float* __restrict__ b) {
    int n = (blockIdx.x * blockDim.x + threadIdx.x) >> 5;
    if (n >= NN) return;
    int lane = threadIdx.x & 31;
    int hl = lane & 3;
    int hsrc = lane >> 3;
    int beg = g_off[n], end = g_off[n + 1];

    float4 ad = *(const float4*)&g_adst[n * 4];
    float adl = (hl == 0) ? ad.x : (hl == 1) ? ad.y : (hl == 2) ? ad.z : ad.w;

    float4 acc = make_float4(0.f, 0.f, 0.f, 0.f);
    float s = 0.f;
    int i = beg;
    for (; i + 4 <= end; i += 4) {
        int sv0 = g_csrc[i], sv1 = g_csrc[i + 1], sv2 = g_csrc[i + 2], sv3 = g_csrc[i + 3];
        float a0 = __ldg(&g_asrc[sv0 * 4 + hl]);
        float a1 = __ldg(&g_asrc[sv1 * 4 + hl]);
        float a2 = __ldg(&g_asrc[sv2 * 4 + hl]);
        float a3 = __ldg(&g_asrc[sv3 * 4 + hl]);
        float4 h0 = *(const float4*)&g_t[sv0 * 128 + lane * 4];
        float4 h1 = *(const float4*)&g_t[sv1 * 128 + lane * 4];
        float4 h2 = *(const float4*)&g_t[sv2 * 128 + lane * 4];
        float4 h3 = *(const float4*)&g_t[sv3 * 128 + lane * 4];
        float p0 = pexp(lrelu(a0 + adl));
        float p1 = pexp(lrelu(a1 + adl));
        float p2 = pexp(lrelu(a2 + adl));
        float p3 = pexp(lrelu(a3 + adl));
        s += (p0 + p1) + (p2 + p3);
        float q0 = __shfl_sync(0xffffffffu, p0, hsrc);
        float q1 = __shfl_sync(0xffffffffu, p1, hsrc);
        float q2 = __shfl_sync(0xffffffffu, p2, hsrc);
        float q3 = __shfl_sync(0xffffffffu, p3, hsrc);
        acc.x = fmaf(q0, h0.x, acc.x); acc.y = fmaf(q0, h0.y, acc.y);
        acc.z = fmaf(q0, h0.z, acc.z); acc.w = fmaf(q0, h0.w, acc.w);
        acc.x = fmaf(q1, h1.x, acc.x); acc.y = fmaf(q1, h1.y, acc.y);
        acc.z = fmaf(q1, h1.z, acc.z); acc.w = fmaf(q1, h1.w, acc.w);
        acc.x = fmaf(q2, h2.x, acc.x); acc.y = fmaf(q2, h2.y, acc.y);
        acc.z = fmaf(q2, h2.z, acc.z); acc.w = fmaf(q2, h2.w, acc.w);
        acc.x = fmaf(q3, h3.x, acc.x); acc.y = fmaf(q3, h3.y, acc.y);
        acc.z = fmaf(q3, h3.z, acc.z); acc.w = fmaf(q3, h3.w, acc.w);
    }
    for (; i < end; i++) {
        int sv = g_csrc[i];
        float a0 = __ldg(&g_asrc[sv * 4 + hl]);
        float4 h0 = *(const float4*)&g_t[sv * 128 + lane * 4];
        float p0 = pexp(lrelu(a0 + adl));
        s += p0;
        float q0 = __shfl_sync(0xffffffffu, p0, hsrc);
        acc.x = fmaf(q0, h0.x, acc.x); acc.y = fmaf(q0, h0.y, acc.y);
        acc.z = fmaf(q0, h0.z, acc.z); acc.w = fmaf(q0, h0.w, acc.w);
    }

    // self loop
    float4 asf = *(const float4*)&g_asrc[n * 4];
    float asl = (hl == 0) ? asf.x : (hl == 1) ? asf.y : (hl == 2) ? asf.z : asf.w;
    float pself = pexp(lrelu(asl + adl));
    s += pself;
    float sh = __shfl_sync(0xffffffffu, s, hsrc);
    float ph = __shfl_sync(0xffffffffu, pself, hsrc);

    float4 ts = *(const float4*)&g_t[n * 128 + lane * 4];
    float4 bv = *(const float4*)&b[lane * 4];
    float inv = 1.f / sh;
    float4 pr = *(const float4*)&g_prev[n * 128 + lane * 4];
    float4 v;
    v.x = elu(fmaf(ph, ts.x, acc.x) * inv + bv.x) + pr.x;
    v.y = elu(fmaf(ph, ts.y, acc.y) * inv + bv.y) + pr.y;
    v.z = elu(fmaf(ph, ts.z, acc.z) * inv + bv.z) + pr.z;
    v.w = elu(fmaf(ph, ts.w, acc.w) * inv + bv.w) + pr.w;
    *(float4*)&g_prev[n * 128 + lane * 4] = v;
}

// ================= layer 3 GEMM: g_prev[N,128] @ W3[128,32] =====================
// block 128 threads, 32 nodes; thread: 2 nodes x 4 cols
__global__ void k_gemm3(const float* __restrict__ W,
                        const float* __restrict__ aS, const float* __restrict__ aD) {
    __shared__ float xs[32][128];
    __shared__ float ws[128][32];
    int t = threadIdx.x;
    int nb = blockIdx.x * 32;
    {
        const float4* srcp = (const float4*)&g_prev[nb * 128];
        float4* d = (float4*)xs;
#pragma unroll
        for (int r = 0; r < 8; r++) d[t + 128 * r] = srcp[t + 128 * r];
        const float4* wsrc = (const float4*)W;
        float4* wd = (float4*)ws;
#pragma unroll
        for (int r = 0; r < 8; r++) wd[t + 128 * r] = wsrc[t + 128 * r];
    }
    __syncthreads();

    int cg = t & 7;         // cols cg*4..+3
    int ng = t >> 3;        // nodes ng*2, ng*2+1
    float4 a0 = make_float4(0,0,0,0), a1 = a0;
#pragma unroll 4
    for (int k = 0; k < 128; k++) {
        float4 wv = *(const float4*)&ws[k][cg * 4];
        float x0 = xs[ng * 2 + 0][k];
        float x1 = xs[ng * 2 + 1][k];
        a0.x = fmaf(x0, wv.x, a0.x); a0.y = fmaf(x0, wv.y, a0.y);
        a0.z = fmaf(x0, wv.z, a0.z); a0.w = fmaf(x0, wv.w, a0.w);
        a1.x = fmaf(x1, wv.x, a1.x); a1.y = fmaf(x1, wv.y, a1.y);
        a1.z = fmaf(x1, wv.z, a1.z); a1.w = fmaf(x1, wv.w, a1.w);
    }

    float4 aSv = *(const float4*)&aS[cg * 4];
    float4 aDv = *(const float4*)&aD[cg * 4];
    float4 accs[2] = {a0, a1};
#pragma unroll
    for (int j = 0; j < 2; j++) {
        int node = nb + ng * 2 + j;
        *(float4*)&g_t[node * 32 + cg * 4] = accs[j];
        float ps = accs[j].x * aSv.x + accs[j].y * aSv.y + accs[j].z * aSv.z + accs[j].w * aSv.w;
        float pd = accs[j].x * aDv.x + accs[j].y * aDv.y + accs[j].z * aDv.z + accs[j].w * aDv.w;
#pragma unroll
        for (int o = 4; o; o >>= 1) {
            ps += __shfl_xor_sync(0xffffffffu, ps, o);
            pd += __shfl_xor_sync(0xffffffffu, pd, o);
        }
        if (cg == 0) {
            g_asrc[node] = ps;
            g_adst[node] = pd;
        }
    }
}

// ================= layer 3 gather + output heads ================================
__global__ void k_gather1(const float* __restrict__ b3,
                          const float* __restrict__ rw, const float* __restrict__ rb,
                          const float* __restrict__ cw, const float* __restrict__ cb,
                          float* __restrict__ out) {
    int n = (blockIdx.x * blockDim.x + threadIdx.x) >> 5;
    if (n >= NN) return;
    int lane = threadIdx.x & 31;
    int beg = g_off[n], end = g_off[n + 1];

    float adn = g_adst[n];
    float acc = 0.f, s = 0.f;
    int i = beg;
    for (; i + 4 <= end; i += 4) {
        int sv0 = g_csrc[i], sv1 = g_csrc[i + 1], sv2 = g_csrc[i + 2], sv3 = g_csrc[i + 3];
        float a0 = __ldg(&g_asrc[sv0]);
        float a1 = __ldg(&g_asrc[sv1]);
        float a2 = __ldg(&g_asrc[sv2]);
        float a3 = __ldg(&g_asrc[sv3]);
        float h0 = g_t[sv0 * 32 + lane];
        float h1 = g_t[sv1 * 32 + lane];
        float h2 = g_t[sv2 * 32 + lane];
        float h3 = g_t[sv3 * 32 + lane];
        float p0 = pexp(lrelu(a0 + adn));
        float p1 = pexp(lrelu(a1 + adn));
        float p2 = pexp(lrelu(a2 + adn));
        float p3 = pexp(lrelu(a3 + adn));
        s += (p0 + p1) + (p2 + p3);
        acc = fmaf(p0, h0, acc);
        acc = fmaf(p1, h1, acc);
        acc = fmaf(p2, h2, acc);
        acc = fmaf(p3, h3, acc);
    }
    for (; i < end; i++) {
        int sv = g_csrc[i];
        float p = pexp(lrelu(__ldg(&g_asrc[sv]) + adn));
        s += p;
        acc = fmaf(p, g_t[sv * 32 + lane], acc);
    }

    float ps = pexp(lrelu(g_asrc[n] + adn));
    s += ps;
    float val = elu(fmaf(ps, g_t[n * 32 + lane], acc) / s + b3[lane]);

    float r = val * rw[lane], cl = val * cw[lane];
#pragma unroll
    for (int o = 16; o; o >>= 1) {
        r += __shfl_xor_sync(0xffffffffu, r, o);
        cl += __shfl_xor_sync(0xffffffffu, cl, o);
    }
    if (lane == 0) {
        out[n] = r + rb[0];
        out[NN + n] = cl + cb[0];
    }
}

// ================= launch =======================================================
extern "C" void kernel_launch(void* const* d_in, const int* in_sizes, int n_in,
                              void* d_out, int out_size) {
    const float* x    = (const float*)d_in[0];
    const int*   ei   = (const int*)d_in[1];
    const float* W1   = (const float*)d_in[2];
    const float* aS1  = (const float*)d_in[3];
    const float* aD1  = (const float*)d_in[4];
    const float* b1   = (const float*)d_in[5];
    const float* W2   = (const float*)d_in[6];
    const float* aS2  = (const float*)d_in[7];
    const float* aD2  = (const float*)d_in[8];
    const float* b2   = (const float*)d_in[9];
    const float* W3   = (const float*)d_in[10];
    const float* aS3  = (const float*)d_in[11];
    const float* aD3  = (const float*)d_in[12];
    const float* b3   = (const float*)d_in[13];
    const float* regw = (const float*)d_in[14];
    const float* regb = (const float*)d_in[15];
    const float* clsw = (const float*)d_in[16];
    const float* clsb = (const float*)d_in[17];
    float* out = (float*)d_out;

    const int* src = ei;
    const int* dst = ei + NE;

    // CSR by dst
    k_zero<<<391, 256>>>();
    k_hist<<<6250, 256>>>(dst);
    k_bsum<<<391, 256>>>();
    k_bscan<<<1, 512>>>();
    k_local<<<391, 256>>>();
    k_reorder<<<6250, 256>>>(src, dst);

    // layer 1 (x-space aggregation; no gemm1 needed)
    k_prep1<<<1, 64>>>(W1, aS1, aD1);
    k_logits1<<<(NN * 4 + 255) / 256, 256>>>(x);
    k_gx<<<12500, 256>>>(x, W1, b1);

    // layer 2 (+ residual)
    k_gemm2<<<3125, 256>>>(W2, aS2, aD2);
    k_gather4<<<12500, 256>>>(b2);

    // layer 3 + output heads
    k_gemm3<<<3125, 128>>>(W3, aS3, aD3);
    k_gather1<<<12500, 256>>>(b3, regw, regb, clsw, clsb, out);
}